// round 1
// baseline (speedup 1.0000x reference)
#include <cuda_runtime.h>

// ImprovedVectorizationLoss: fused masked-L1 + BCE + continuity + recon-MSE loss.
// Inputs (metadata order):
//   d_in[0] predictions  (B, M, 9)  f32
//   d_in[1] targets      (B, M, 9)  f32
//   d_in[2] reconstructed(B, 1, 128, 128) f32
//   d_in[3] images       (B, 1, 128, 128) f32
// Output: scalar f32.

#define M_ROW 4096
#define TPB 256
#define CHUNK 16              // M_ROW / TPB
#define RECON_BLOCKS 128
#define MAX_BLOCKS 2048
#define REC_W9 (M_ROW * 9)    // floats per row
#define F4_PER_ROW (REC_W9 / 4)          // 9216
#define F4_ITERS (F4_PER_ROW / TPB)      // 36

// Per-block partial sums: [coord, width, bce, n_valid, cont, recon]
// Rewritten completely on every launch -> deterministic under graph replay.
__device__ float g_partials[MAX_BLOCKS][6];

__device__ __forceinline__ float warpReduceSumF(float v) {
#pragma unroll
    for (int o = 16; o > 0; o >>= 1) v += __shfl_down_sync(0xffffffffu, v, o);
    return v;
}

__device__ __forceinline__ double warpReduceSumD(double v) {
#pragma unroll
    for (int o = 16; o > 0; o >>= 1) v += __shfl_down_sync(0xffffffffu, v, o);
    return v;
}

__global__ __launch_bounds__(TPB) void loss_main_kernel(
    const float* __restrict__ preds, const float* __restrict__ tgts,
    const float* __restrict__ rec,   const float* __restrict__ img,
    int B, int nrec)
{
    __shared__ float2 s34[M_ROW];     // predictions channels 4,5 (32 KB)
    __shared__ float  smask[M_ROW];   // validity mask (16 KB)
    __shared__ int    schunk[TPB];    // per-chunk min valid index
    __shared__ float  swred[6][8];    // block reduction staging

    const int tid  = threadIdx.x;
    const int bid  = blockIdx.x;
    const int lane = tid & 31;
    const int wid  = tid >> 5;

    float coordS = 0.f, widthS = 0.f, bceS = 0.f, nvS = 0.f, contS = 0.f, reconS = 0.f;

    if (bid < B) {
        const size_t rowbase = (size_t)bid * REC_W9;

        // ---- Phase 1: stage validity column (targets channel 8) into shared ----
        // Interleaved m = tid + k*TPB -> warp spans 9 lines/load, cheap; also
        // effectively prefetches the targets row into L1/L2 for phase 2.
#pragma unroll
        for (int k = 0; k < CHUNK; k++) {
            int m = tid + k * TPB;
            float t8 = __ldg(&tgts[rowbase + (size_t)m * 9 + 8]);
            smask[m] = (t8 > 0.5f) ? 1.0f : 0.0f;
        }
        __syncthreads();

        // ---- Phase 2: flat coalesced float4 stream over preds & targets ----
        const float4* p4 = reinterpret_cast<const float4*>(preds + rowbase);
        const float4* t4 = reinterpret_cast<const float4*>(tgts + rowbase);
#pragma unroll 4
        for (int k = 0; k < F4_ITERS; k++) {
            int idx4 = tid + k * TPB;
            float4 p = p4[idx4];
            float4 t = t4[idx4];
            int e0 = idx4 * 4;
            int m  = e0 / 9;
            int c  = e0 - m * 9;
            float pe[4] = {p.x, p.y, p.z, p.w};
            float te[4] = {t.x, t.y, t.z, t.w};
#pragma unroll
            for (int i = 0; i < 4; i++) {
                float pv = pe[i], tv = te[i];
                if (c < 6) {
                    coordS += fabsf(pv - tv) * smask[m];
                    if (c == 4)      s34[m].x = pv;
                    else if (c == 5) s34[m].y = pv;
                } else if (c < 8) {
                    widthS += fabsf(pv - tv) * smask[m];
                } else {
                    // c == 8: BCE term; tv is target validity itself.
                    float pc = fminf(fmaxf(pv, 1e-7f), 1.0f - 1e-7f);
                    bceS += -(tv * logf(pc) + (1.0f - tv) * logf(1.0f - pc));
                    nvS  += smask[m];
                }
                if (++c == 9) { c = 0; ++m; }
            }
        }
        __syncthreads();

        // ---- Phase 3: continuity (next-valid-index via suffix min) ----
        int cmin = M_ROW;
        {
            const int mbase = tid * CHUNK;
#pragma unroll
            for (int j = CHUNK - 1; j >= 0; j--) {
                if (smask[mbase + j] != 0.0f) cmin = mbase + j;
            }
        }
        schunk[tid] = cmin;
        __syncthreads();
        // inclusive suffix-min scan over 256 chunk minima
#pragma unroll
        for (int off = 1; off < TPB; off <<= 1) {
            int v = schunk[tid];
            if (tid + off < TPB) v = min(v, schunk[tid + off]);
            __syncthreads();
            schunk[tid] = v;
            __syncthreads();
        }
        int running = (tid < TPB - 1) ? schunk[tid + 1] : M_ROW;
        {
            const int mbase = tid * CHUNK;
#pragma unroll
            for (int j = CHUNK - 1; j >= 0; j--) {
                int m = mbase + j;
                if (smask[m] != 0.0f) {
                    if (running < M_ROW) {
                        float2 a = s34[m];
                        float2 b = s34[running];
                        contS += 0.5f * (fabsf(a.x - b.x) + fabsf(a.y - b.y));
                    }
                    running = m;
                }
            }
        }
    } else {
        // ---- Recon MSE blocks: grid-stride float4 over (rec - img)^2 ----
        const int rb = bid - B;
        const float4* r4 = reinterpret_cast<const float4*>(rec);
        const float4* i4 = reinterpret_cast<const float4*>(img);
        const int n4 = nrec >> 2;
        for (int i = rb * TPB + tid; i < n4; i += RECON_BLOCKS * TPB) {
            float4 r = r4[i], m = i4[i];
            float dx = r.x - m.x, dy = r.y - m.y, dz = r.z - m.z, dw = r.w - m.w;
            reconS += dx * dx + dy * dy + dz * dz + dw * dw;
        }
    }

    // ---- Block reduce 6 partials, write to g_partials[bid] ----
    float vals[6] = {coordS, widthS, bceS, nvS, contS, reconS};
#pragma unroll
    for (int q = 0; q < 6; q++) {
        float v = warpReduceSumF(vals[q]);
        if (lane == 0) swred[q][wid] = v;
    }
    __syncthreads();
    if (wid == 0) {
#pragma unroll
        for (int q = 0; q < 6; q++) {
            float v = (lane < (TPB / 32)) ? swred[q][lane] : 0.0f;
            v = warpReduceSumF(v);
            if (lane == 0) g_partials[bid][q] = v;
        }
    }
}

__global__ __launch_bounds__(256) void loss_final_kernel(
    float* __restrict__ out, int nblocks, int B, int M, int nrec)
{
    __shared__ double sd[6][8];
    const int tid  = threadIdx.x;
    const int lane = tid & 31;
    const int w    = tid >> 5;

    double acc[6] = {0, 0, 0, 0, 0, 0};
    for (int i = tid; i < nblocks; i += 256) {
#pragma unroll
        for (int q = 0; q < 6; q++) acc[q] += (double)g_partials[i][q];
    }
#pragma unroll
    for (int q = 0; q < 6; q++) {
        double v = warpReduceSumD(acc[q]);
        if (lane == 0) sd[q][w] = v;
    }
    __syncthreads();
    if (tid == 0) {
        double t[6];
#pragma unroll
        for (int q = 0; q < 6; q++) {
            double s = 0.0;
            for (int j = 0; j < 8; j++) s += sd[q][j];
            t[q] = s;
        }
        double nv = t[3];
        double coord    = (nv > 0.0) ? t[0] / fmax(nv * 6.0, 1.0) : 0.0;
        double width    = (nv > 0.0) ? t[1] / fmax(nv * 2.0, 1.0) : 0.0;
        double validity = t[2] / ((double)B * (double)M);
        double cont     = t[4] / (double)B;
        double recon    = t[5] / (double)nrec;
        out[0] = (float)(coord + width + 2.0 * validity + 0.2 * cont + 0.1 * recon);
    }
}

extern "C" void kernel_launch(void* const* d_in, const int* in_sizes, int n_in,
                              void* d_out, int out_size)
{
    const float* preds = (const float*)d_in[0];
    const float* tgts  = (const float*)d_in[1];
    const float* rec   = (const float*)d_in[2];
    const float* img   = (const float*)d_in[3];

    const int B    = in_sizes[0] / REC_W9;   // 256 for the reference shapes
    const int nrec = in_sizes[2];            // B * 128 * 128

    const int nblocks = B + RECON_BLOCKS;    // 384

    loss_main_kernel<<<nblocks, TPB>>>(preds, tgts, rec, img, B, nrec);
    loss_final_kernel<<<1, 256>>>((float*)d_out, nblocks, B, M_ROW, nrec);
}

// round 2
// speedup vs baseline: 1.7858x; 1.7858x over previous
#include <cuda_runtime.h>

// ImprovedVectorizationLoss: fused masked-L1 + BCE + continuity + recon-MSE.
// Inputs: preds (B,M,9) f32, tgts (B,M,9) f32, rec (B,1,128,128) f32, img same.
// Output: scalar f32.

#define M_ROW 4096
#define TPB   256
#define SEGS  8                      // segments per row
#define SEG   (M_ROW / SEGS)         // 512 records per segment
#define TILE  256                    // records per smem tile
#define NTILE (SEG / TILE)           // 2
#define RECON_BLOCKS 1024
#define MAX_BLOCKS 6144
#define BMAX 512
#define EPSV 1e-7f

// Per-block partials: [coord, width, bce, n_valid, cont, recon]
__device__ float g_partials[MAX_BLOCKS][6];
// Per (row,segment) boundary info for continuity fixup.
__device__ int    g_first_idx[BMAX * SEGS];   // local idx in [0,SEG) or SEG if empty
__device__ float2 g_first_p45[BMAX * SEGS];
__device__ float2 g_last_p45[BMAX * SEGS];

__device__ __forceinline__ float warpReduceSumF(float v) {
#pragma unroll
    for (int o = 16; o > 0; o >>= 1) v += __shfl_down_sync(0xffffffffu, v, o);
    return v;
}
__device__ __forceinline__ double warpReduceSumD(double v) {
#pragma unroll
    for (int o = 16; o > 0; o >>= 1) v += __shfl_down_sync(0xffffffffu, v, o);
    return v;
}

__global__ __launch_bounds__(TPB) void loss_main_kernel(
    const float* __restrict__ preds, const float* __restrict__ tgts,
    const float* __restrict__ rec,   const float* __restrict__ img,
    int B, int nrec)
{
    __shared__ float  sp[TILE * 9];        // 9 KB staged predictions tile
    __shared__ float  st[TILE * 9];        // 9 KB staged targets tile
    __shared__ float2 s45[SEG];            // 4 KB pred channels 4,5
    __shared__ unsigned char smk[SEG];     // validity per record
    __shared__ int    schunk[TPB];
    __shared__ float  swred[6][8];

    const int tid  = threadIdx.x;
    const int bid  = blockIdx.x;
    const int lane = tid & 31;
    const int wid  = tid >> 5;
    const int nseg_blocks = B * SEGS;

    float coordS = 0.f, widthS = 0.f, bceS = 0.f, nvS = 0.f, contS = 0.f, reconS = 0.f;

    if (bid < nseg_blocks) {
        const int row = bid / SEGS;
        const int seg = bid - row * SEGS;
        const size_t segbase = ((size_t)row * M_ROW + (size_t)seg * SEG) * 9;

#pragma unroll
        for (int tile = 0; tile < NTILE; tile++) {
            // ---- stage one 256-record tile (coalesced float4) ----
            const float4* p4 = reinterpret_cast<const float4*>(preds + segbase + (size_t)tile * TILE * 9);
            const float4* t4 = reinterpret_cast<const float4*>(tgts  + segbase + (size_t)tile * TILE * 9);
            float4* sp4 = reinterpret_cast<float4*>(sp);
            float4* st4 = reinterpret_cast<float4*>(st);
            const int NF4 = TILE * 9 / 4;   // 576
#pragma unroll
            for (int i = tid; i < NF4; i += TPB) {
                sp4[i] = p4[i];
                st4[i] = t4[i];
            }
            __syncthreads();

            // ---- one record per thread, branch-free ----
            const float* pr = sp + tid * 9;
            const float* tr = st + tid * 9;
            float t8   = tr[8];
            float mask = (t8 > 0.5f) ? 1.0f : 0.0f;

            float c0 = fabsf(pr[0] - tr[0]) + fabsf(pr[1] - tr[1]) + fabsf(pr[2] - tr[2])
                     + fabsf(pr[3] - tr[3]) + fabsf(pr[4] - tr[4]) + fabsf(pr[5] - tr[5]);
            coordS += c0 * mask;
            float w0 = fabsf(pr[6] - tr[6]) + fabsf(pr[7] - tr[7]);
            widthS += w0 * mask;

            float p  = fminf(fmaxf(pr[8], EPSV), 1.0f - EPSV);
            bceS    += -(t8 * __logf(p) + (1.0f - t8) * __logf(1.0f - p));
            nvS     += mask;

            int jseg = tile * TILE + tid;
            s45[jseg] = make_float2(pr[4], pr[5]);
            smk[jseg] = (unsigned char)(t8 > 0.5f ? 1 : 0);
            __syncthreads();   // protect sp/st before next tile overwrite
        }

        // ---- segment-local continuity: suffix-min over 512 entries ----
        {
            int j0 = 2 * tid, j1 = 2 * tid + 1;
            int p0 = smk[j0] ? j0 : SEG;
            int p1 = smk[j1] ? j1 : SEG;
            schunk[tid] = min(p0, p1);
        }
        __syncthreads();
#pragma unroll
        for (int off = 1; off < TPB; off <<= 1) {
            int v = schunk[tid];
            if (tid + off < TPB) v = min(v, schunk[tid + off]);
            __syncthreads();
            schunk[tid] = v;
            __syncthreads();
        }
        {
            const int rs = row * SEGS + seg;
            int running = (tid < TPB - 1) ? schunk[tid + 1] : SEG;
#pragma unroll
            for (int jj = 1; jj >= 0; jj--) {
                int j = 2 * tid + jj;
                if (smk[j]) {
                    if (running < SEG) {
                        float2 a = s45[j], b = s45[running];
                        contS += 0.5f * (fabsf(a.x - b.x) + fabsf(a.y - b.y));
                    } else {
                        g_last_p45[rs] = s45[j];   // segment's last valid record
                    }
                    running = j;
                }
            }
            if (tid == 0) {
                int f = schunk[0];
                g_first_idx[rs] = f;
                if (f < SEG) g_first_p45[rs] = s45[f];
            }
        }
    } else {
        // ---- recon MSE blocks ----
        const int rb = bid - nseg_blocks;
        const float4* r4 = reinterpret_cast<const float4*>(rec);
        const float4* i4 = reinterpret_cast<const float4*>(img);
        const int n4 = nrec >> 2;
        for (int i = rb * TPB + tid; i < n4; i += RECON_BLOCKS * TPB) {
            float4 r = r4[i], m = i4[i];
            float dx = r.x - m.x, dy = r.y - m.y, dz = r.z - m.z, dw = r.w - m.w;
            reconS += dx * dx + dy * dy + dz * dz + dw * dw;
        }
    }

    // ---- block reduce 6 partials ----
    float vals[6] = {coordS, widthS, bceS, nvS, contS, reconS};
#pragma unroll
    for (int q = 0; q < 6; q++) {
        float v = warpReduceSumF(vals[q]);
        if (lane == 0) swred[q][wid] = v;
    }
    __syncthreads();
    if (wid == 0) {
#pragma unroll
        for (int q = 0; q < 6; q++) {
            float v = (lane < (TPB / 32)) ? swred[q][lane] : 0.0f;
            v = warpReduceSumF(v);
            if (lane == 0) g_partials[bid][q] = v;
        }
    }
}

__global__ __launch_bounds__(256) void loss_final_kernel(
    float* __restrict__ out, int nblocks, int B, int nrec)
{
    __shared__ double sd[6][8];
    const int tid  = threadIdx.x;
    const int lane = tid & 31;
    const int w    = tid >> 5;

    double acc[6] = {0, 0, 0, 0, 0, 0};
    for (int i = tid; i < nblocks; i += 256) {
#pragma unroll
        for (int q = 0; q < 6; q++) acc[q] += (double)g_partials[i][q];
    }

    // ---- cross-segment continuity boundary pairs (one row per thread) ----
    for (int r = tid; r < B; r += 256) {
        float2 nf = make_float2(0.f, 0.f);
        bool have = false;
        for (int s = SEGS - 1; s >= 0; s--) {
            int rs = r * SEGS + s;
            if (g_first_idx[rs] < SEG) {
                if (have) {
                    float2 l = g_last_p45[rs];
                    acc[4] += 0.5 * ((double)fabsf(l.x - nf.x) + (double)fabsf(l.y - nf.y));
                }
                nf = g_first_p45[rs];
                have = true;
            }
        }
    }

#pragma unroll
    for (int q = 0; q < 6; q++) {
        double v = warpReduceSumD(acc[q]);
        if (lane == 0) sd[q][w] = v;
    }
    __syncthreads();
    if (tid == 0) {
        double t[6];
#pragma unroll
        for (int q = 0; q < 6; q++) {
            double s = 0.0;
            for (int j = 0; j < 8; j++) s += sd[q][j];
            t[q] = s;
        }
        double nv = t[3];
        double coord    = (nv > 0.0) ? t[0] / fmax(nv * 6.0, 1.0) : 0.0;
        double width    = (nv > 0.0) ? t[1] / fmax(nv * 2.0, 1.0) : 0.0;
        double validity = t[2] / ((double)B * (double)M_ROW);
        double cont     = t[4] / (double)B;
        double recon    = t[5] / (double)nrec;
        out[0] = (float)(coord + width + 2.0 * validity + 0.2 * cont + 0.1 * recon);
    }
}

extern "C" void kernel_launch(void* const* d_in, const int* in_sizes, int n_in,
                              void* d_out, int out_size)
{
    const float* preds = (const float*)d_in[0];
    const float* tgts  = (const float*)d_in[1];
    const float* rec   = (const float*)d_in[2];
    const float* img   = (const float*)d_in[3];

    const int B    = in_sizes[0] / (M_ROW * 9);   // 256 for reference shapes
    const int nrec = in_sizes[2];

    const int nblocks = B * SEGS + RECON_BLOCKS;

    loss_main_kernel<<<nblocks, TPB>>>(preds, tgts, rec, img, B, nrec);
    loss_final_kernel<<<1, 256>>>((float*)d_out, nblocks, B, nrec);
}

// round 3
// speedup vs baseline: 2.5538x; 1.4300x over previous
#include <cuda_runtime.h>

// ImprovedVectorizationLoss: fused masked-L1 + BCE + continuity + recon-MSE.
// Single persistent-result kernel: per-block partials -> global atomics;
// last block does cross-segment continuity fixup + final scalar, then
// resets the accumulators/ticket so graph replays are self-consistent.

#define M_ROW 4096
#define TPB   256
#define SEGS  8
#define SEG   (M_ROW / SEGS)         // 512
#define TILE  256
#define NTILE (SEG / TILE)           // 2
#define RECON_BLOCKS 1024
#define BMAX  512
#define EPSV  1e-7f

__device__ float        g_acc[6];                  // [coord,width,bce,nvalid,cont,recon]
__device__ unsigned int g_ticket;
__device__ int          g_first_idx[BMAX * SEGS];
__device__ float2       g_first_p45[BMAX * SEGS];
__device__ float2       g_last_p45[BMAX * SEGS];

__device__ __forceinline__ float warpReduceSumF(float v) {
#pragma unroll
    for (int o = 16; o > 0; o >>= 1) v += __shfl_down_sync(0xffffffffu, v, o);
    return v;
}

__global__ __launch_bounds__(TPB) void loss_fused_kernel(
    const float* __restrict__ preds, const float* __restrict__ tgts,
    const float* __restrict__ rec,   const float* __restrict__ img,
    float* __restrict__ out, int B, int nrec, int nblocks)
{
    __shared__ float  sp[TILE * 9];
    __shared__ float  st[TILE * 9];
    __shared__ float2 s45[SEG];
    __shared__ unsigned char smk[SEG];
    __shared__ int    schunk[TPB];
    __shared__ float  swred[6][8];
    __shared__ bool   s_is_last;

    const int tid  = threadIdx.x;
    const int bid  = blockIdx.x;
    const int lane = tid & 31;
    const int wid  = tid >> 5;
    const int nseg_blocks = B * SEGS;

    float coordS = 0.f, widthS = 0.f, bceS = 0.f, nvS = 0.f, contS = 0.f, reconS = 0.f;

    if (bid < nseg_blocks) {
        const int row = bid / SEGS;
        const int seg = bid - row * SEGS;
        const size_t segbase = ((size_t)row * M_ROW + (size_t)seg * SEG) * 9;

#pragma unroll
        for (int tile = 0; tile < NTILE; tile++) {
            const float4* p4 = reinterpret_cast<const float4*>(preds + segbase + (size_t)tile * TILE * 9);
            const float4* t4 = reinterpret_cast<const float4*>(tgts  + segbase + (size_t)tile * TILE * 9);
            float4* sp4 = reinterpret_cast<float4*>(sp);
            float4* st4 = reinterpret_cast<float4*>(st);
            const int NF4 = TILE * 9 / 4;   // 576
#pragma unroll
            for (int i = tid; i < NF4; i += TPB) {
                sp4[i] = p4[i];
                st4[i] = t4[i];
            }
            __syncthreads();

            const float* pr = sp + tid * 9;
            const float* tr = st + tid * 9;
            float t8   = tr[8];
            float mask = (t8 > 0.5f) ? 1.0f : 0.0f;

            coordS += (fabsf(pr[0] - tr[0]) + fabsf(pr[1] - tr[1]) + fabsf(pr[2] - tr[2])
                     + fabsf(pr[3] - tr[3]) + fabsf(pr[4] - tr[4]) + fabsf(pr[5] - tr[5])) * mask;
            widthS += (fabsf(pr[6] - tr[6]) + fabsf(pr[7] - tr[7])) * mask;

            float p = fminf(fmaxf(pr[8], EPSV), 1.0f - EPSV);
            bceS   += -(t8 * __logf(p) + (1.0f - t8) * __logf(1.0f - p));
            nvS    += mask;

            int jseg = tile * TILE + tid;
            s45[jseg] = make_float2(pr[4], pr[5]);
            smk[jseg] = (unsigned char)(t8 > 0.5f ? 1 : 0);
            __syncthreads();
        }

        // segment-local continuity via suffix-min over 512 entries
        {
            int j0 = 2 * tid, j1 = 2 * tid + 1;
            int p0 = smk[j0] ? j0 : SEG;
            int p1 = smk[j1] ? j1 : SEG;
            schunk[tid] = min(p0, p1);
        }
        __syncthreads();
#pragma unroll
        for (int off = 1; off < TPB; off <<= 1) {
            int v = schunk[tid];
            if (tid + off < TPB) v = min(v, schunk[tid + off]);
            __syncthreads();
            schunk[tid] = v;
            __syncthreads();
        }
        {
            const int rs = bid;   // == row*SEGS + seg
            int running = (tid < TPB - 1) ? schunk[tid + 1] : SEG;
#pragma unroll
            for (int jj = 1; jj >= 0; jj--) {
                int j = 2 * tid + jj;
                if (smk[j]) {
                    if (running < SEG) {
                        float2 a = s45[j], b = s45[running];
                        contS += 0.5f * (fabsf(a.x - b.x) + fabsf(a.y - b.y));
                    } else {
                        g_last_p45[rs] = s45[j];
                    }
                    running = j;
                }
            }
            if (tid == 0) {
                int f = schunk[0];
                g_first_idx[rs] = f;
                if (f < SEG) g_first_p45[rs] = s45[f];
            }
        }
    } else {
        const int rb = bid - nseg_blocks;
        const float4* r4 = reinterpret_cast<const float4*>(rec);
        const float4* i4 = reinterpret_cast<const float4*>(img);
        const int n4 = nrec >> 2;
        for (int i = rb * TPB + tid; i < n4; i += RECON_BLOCKS * TPB) {
            float4 r = r4[i], m = i4[i];
            float dx = r.x - m.x, dy = r.y - m.y, dz = r.z - m.z, dw = r.w - m.w;
            reconS += dx * dx + dy * dy + dz * dz + dw * dw;
        }
    }

    // ---- block reduce + global atomic accumulate ----
    float vals[6] = {coordS, widthS, bceS, nvS, contS, reconS};
#pragma unroll
    for (int q = 0; q < 6; q++) {
        float v = warpReduceSumF(vals[q]);
        if (lane == 0) swred[q][wid] = v;
    }
    __syncthreads();
    if (wid == 0 && lane < 6) {
        float v = 0.f;
#pragma unroll
        for (int j = 0; j < 8; j++) v += swred[lane][j];
        atomicAdd(&g_acc[lane], v);
    }

    // ---- last-block finalize ----
    __threadfence();
    if (tid == 0) {
        unsigned int t = atomicAdd(&g_ticket, 1u);
        s_is_last = (t == (unsigned int)(nblocks - 1));
    }
    __syncthreads();
    if (!s_is_last) return;
    __threadfence();   // acquire: make all blocks' writes visible

    // cross-segment continuity fixup: one row per thread, prefetched loads
    float fix = 0.f;
    for (int r = tid; r < B; r += TPB) {
        int    fidx[SEGS];
        float2 fp[SEGS], lp[SEGS];
#pragma unroll
        for (int s = 0; s < SEGS; s++) {
            int rs = r * SEGS + s;
            fidx[s] = g_first_idx[rs];
            fp[s]   = g_first_p45[rs];
            lp[s]   = g_last_p45[rs];
        }
        float2 nf = make_float2(0.f, 0.f);
        bool have = false;
#pragma unroll
        for (int s = SEGS - 1; s >= 0; s--) {
            if (fidx[s] < SEG) {
                if (have) fix += 0.5f * (fabsf(lp[s].x - nf.x) + fabsf(lp[s].y - nf.y));
                nf = fp[s];
                have = true;
            }
        }
    }
    // reduce fix across the last block
    {
        float v = warpReduceSumF(fix);
        if (lane == 0) swred[0][wid] = v;
    }
    __syncthreads();
    if (tid == 0) {
        float fsum = 0.f;
#pragma unroll
        for (int j = 0; j < 8; j++) fsum += swred[0][j];

        double t0 = (double)g_acc[0], t1 = (double)g_acc[1], t2 = (double)g_acc[2];
        double nv = (double)g_acc[3];
        double t4 = (double)g_acc[4] + (double)fsum;
        double t5 = (double)g_acc[5];

        double coord    = (nv > 0.0) ? t0 / fmax(nv * 6.0, 1.0) : 0.0;
        double width    = (nv > 0.0) ? t1 / fmax(nv * 2.0, 1.0) : 0.0;
        double validity = t2 / ((double)B * (double)M_ROW);
        double cont     = t4 / (double)B;
        double recon    = t5 / (double)nrec;
        out[0] = (float)(coord + width + 2.0 * validity + 0.2 * cont + 0.1 * recon);

        // self-reset for the next graph replay
        g_ticket = 0u;
#pragma unroll
        for (int q = 0; q < 6; q++) g_acc[q] = 0.f;
        __threadfence();
    }
}

extern "C" void kernel_launch(void* const* d_in, const int* in_sizes, int n_in,
                              void* d_out, int out_size)
{
    const float* preds = (const float*)d_in[0];
    const float* tgts  = (const float*)d_in[1];
    const float* rec   = (const float*)d_in[2];
    const float* img   = (const float*)d_in[3];

    const int B    = in_sizes[0] / (M_ROW * 9);
    const int nrec = in_sizes[2];
    const int nblocks = B * SEGS + RECON_BLOCKS;

    loss_fused_kernel<<<nblocks, TPB>>>(preds, tgts, rec, img,
                                        (float*)d_out, B, nrec, nblocks);
}